// round 16
// baseline (speedup 1.0000x reference)
#include <cuda_runtime.h>
#include <cstdint>

#define BB 16
#define NTOK 2049
#define NK 2048
#define CC 1024
#define WS 3072

__device__ float g_qcls[BB * CC];      // zero-init; atomic accum; re-zeroed by k_logits epilogue
__device__ float g_v[BB * CC];
__device__ float g_psum[BB * 512];     // exp partials: [b][bx*4+warp]
__device__ unsigned g_barP = 0;        // k_prep barrier counter (monotonic, replay-safe)
__device__ int g_cnt[BB] = {0};        // per-batch completion counters (self-reset)

// ---------------------------------------------------------------------------
// helpers
// ---------------------------------------------------------------------------
__device__ __forceinline__ void cpa16(unsigned int smem_addr, const void* gptr) {
    asm volatile("cp.async.cg.shared.global [%0], [%1], 16;"
                 :: "r"(smem_addr), "l"(gptr));
}
#define CPA_COMMIT()  asm volatile("cp.async.commit_group;")
#define CPA_WAIT(N)   asm volatile("cp.async.wait_group %0;" :: "n"(N))

// Grid barrier via monotonic counter (all 256 blocks of k_prep are resident).
__device__ __forceinline__ void gridbar(unsigned* ctr, unsigned G) {
    __syncthreads();
    __threadfence();
    if (threadIdx.x == 0) {
        const unsigned my = atomicAdd(ctr, 1u) + 1u;
        const unsigned tgt = ((my - 1u) / G + 1u) * G;
        while (atomicAdd(ctr, 0u) < tgt) __nanosleep(64);
    }
    __syncthreads();
    __threadfence();
}

// ---------------------------------------------------------------------------
// k_prep: fused q_cls + v. grid 256, 256 thr.
// Phase A: q_cls partials (W_q read once chip-wide), atomicAdd -> g_qcls.
// [grid barrier]
// Phase B: v[b,d] = W_k[d,:].q_cls[b,:]; block = (8 d, one bg of 8 batches).
// ---------------------------------------------------------------------------
__global__ __launch_bounds__(256) void k_prep(const float* __restrict__ x,
                                              const float* __restrict__ w) {
    __shared__ float pool[8704];
    const int t   = threadIdx.x;
    const int bid = blockIdx.x;
    const int wid = t >> 5, lane = t & 31;

    // ---------------- Phase A: q_cls partials ----------------
    {
        float* xs  = pool;                // [b][dd] 16x32
        float* red = pool + 512;          // [dg][b][c] 4x16x128
        const int d0 = (bid >> 3) * 32;
        const int c0 = (bid & 7) * 128;

        if (t < 128) {
            const int b = t >> 3, dd = (t & 7) * 4;
            *(float4*)&xs[b * 32 + dd] =
                *(const float4*)&x[(size_t)b * NTOK * CC + d0 + dd];
        }
        __syncthreads();

        const int dg = wid & 3, bg = wid >> 2;
        const int c = c0 + lane * 4;

        float4 a[8];
        #pragma unroll
        for (int j = 0; j < 8; j++) a[j] = make_float4(0.f, 0.f, 0.f, 0.f);

        const float* xb = &xs[bg * 8 * 32];
        #pragma unroll
        for (int i = 0; i < 8; i++) {
            const int dd = dg * 8 + i;
            const float4 w4 = *(const float4*)&w[(size_t)(d0 + dd) * WS + c];
            #pragma unroll
            for (int j = 0; j < 8; j++) {
                const float xv = xb[j * 32 + dd];
                a[j].x = fmaf(w4.x, xv, a[j].x);
                a[j].y = fmaf(w4.y, xv, a[j].y);
                a[j].z = fmaf(w4.z, xv, a[j].z);
                a[j].w = fmaf(w4.w, xv, a[j].w);
            }
        }
        #pragma unroll
        for (int j = 0; j < 8; j++)
            *(float4*)&red[dg * 2048 + (bg * 8 + j) * 128 + lane * 4] = a[j];
        __syncthreads();

        #pragma unroll
        for (int k = 0; k < 8; k++) {
            const int idx = t + 256 * k;             // b = idx>>7, c = idx&127
            const float s = (red[idx] + red[idx + 2048])
                          + (red[idx + 4096] + red[idx + 6144]);
            atomicAdd(&g_qcls[(idx >> 7) * CC + c0 + (idx & 127)], s);
        }
    }

    gridbar(&g_barP, 256);

    // ---------------- Phase B: v ----------------
    {
        float* qs = pool;                 // 8 batches x 1024 = 32KB
        const int bg = bid & 1;
        const int d  = (bid >> 1) * 8 + wid;

        #pragma unroll
        for (int i = 0; i < 8; i++)
            ((float4*)qs)[t + 256 * i] =
                ((const float4*)(g_qcls + bg * 8 * CC))[t + 256 * i];
        __syncthreads();

        const float* wr = w + (size_t)d * WS + CC;
        float acc[8];
        #pragma unroll
        for (int b = 0; b < 8; b++) acc[b] = 0.f;

        #pragma unroll
        for (int i = 0; i < 8; i++) {
            const int cc = i * 128 + lane * 4;
            const float4 w4 = *(const float4*)&wr[cc];
            #pragma unroll
            for (int b = 0; b < 8; b++) {
                const float4 q4 = *(const float4*)&qs[b * CC + cc];
                acc[b] = fmaf(w4.x, q4.x, acc[b]);
                acc[b] = fmaf(w4.y, q4.y, acc[b]);
                acc[b] = fmaf(w4.z, q4.z, acc[b]);
                acc[b] = fmaf(w4.w, q4.w, acc[b]);
            }
        }
        #pragma unroll
        for (int b = 0; b < 8; b++) {
            float a = acc[b];
            #pragma unroll
            for (int o = 16; o; o >>= 1) a += __shfl_xor_sync(0xffffffffu, a, o);
            if (lane == 0) g_v[(bg * 8 + b) * CC + d] = a;
        }
    }
}

// ---------------------------------------------------------------------------
// k_logits (dominant, HBM-bound): grid (128,16), 128 thr, block-wide
// 2-stage cp.async ring, 16 rows/block. Launched with PDL: starts under
// k_prep, issues x prologue immediately, then cudaGridDependencySynchronize()
// before reading g_v. Epilogue: last-block-per-batch normalize (R14-proven).
// ---------------------------------------------------------------------------
__global__ __launch_bounds__(128) void k_logits(const float* __restrict__ x,
                                                float* __restrict__ out) {
    __shared__ float tiles[2 * 4096];
    __shared__ float vsm[CC];
    __shared__ float sp[128];
    __shared__ int lastflag;
    const int b    = blockIdx.y;
    const int bx   = blockIdx.x;
    const int tid  = threadIdx.x;
    const int warp = tid >> 5;
    const int lane = tid & 31;

    const float* xbase = x + ((size_t)b * NTOK + bx * 16 + 1) * CC;
    const unsigned int sb = (unsigned int)__cvta_generic_to_shared(tiles);

    // prologue FIRST — x is launch-stable, overlaps k_prep execution
    #pragma unroll
    for (int k = 0; k < 8; k++)
        cpa16(sb + (k * 512 + tid * 4) * 4, xbase + k * 512 + tid * 4);
    CPA_COMMIT();
    #pragma unroll
    for (int k = 0; k < 8; k++)
        cpa16(sb + (4096 + k * 512 + tid * 4) * 4, xbase + 4096 + k * 512 + tid * 4);
    CPA_COMMIT();

    // HW wait for k_prep completion (deadlock-free, residency-independent)
    cudaGridDependencySynchronize();

    // stage v -> smem -> registers
    #pragma unroll
    for (int i = 0; i < 2; i++)
        ((float4*)vsm)[tid + 128 * i] = ((const float4*)(g_v + b * CC))[tid + 128 * i];
    __syncthreads();
    float4 vr[8];
    #pragma unroll
    for (int i = 0; i < 8; i++) vr[i] = ((const float4*)vsm)[i * 32 + lane];

    float psum = 0.f;

    #pragma unroll
    for (int t = 0; t < 4; t++) {
        if (t == 3) { CPA_WAIT(0); } else { CPA_WAIT(1); }
        __syncthreads();

        const float* buf = tiles + (t & 1) * 4096 + warp * CC;
        float4 a = make_float4(0.f, 0.f, 0.f, 0.f);
        #pragma unroll
        for (int i = 0; i < 8; i++) {
            const float4 xv = ((const float4*)buf)[i * 32 + lane];
            a.x = fmaf(xv.x, vr[i].x, a.x);
            a.y = fmaf(xv.y, vr[i].y, a.y);
            a.z = fmaf(xv.z, vr[i].z, a.z);
            a.w = fmaf(xv.w, vr[i].w, a.w);
        }
        float s = (a.x + a.y) + (a.z + a.w);
        #pragma unroll
        for (int o = 16; o; o >>= 1) s += __shfl_xor_sync(0xffffffffu, s, o);

        if (lane == 0) {
            const float e = __expf(s * 0.03125f);
            out[(b << 11) + bx * 16 + t * 4 + warp] = e;
            psum += e;
        }

        if (t < 2) {
            __syncthreads();
            const int nt = t + 2;
            #pragma unroll
            for (int k = 0; k < 8; k++)
                cpa16(sb + ((nt & 1) * 4096 + k * 512 + tid * 4) * 4,
                      xbase + nt * 4096 + k * 512 + tid * 4);
            CPA_COMMIT();
        }
    }

    if (lane == 0)
        g_psum[b * 512 + bx * 4 + warp] = psum;

    // ---------------- last-block-per-batch normalize ----------------
    __threadfence();
    __syncthreads();
    if (tid == 0)
        lastflag = (atomicAdd(&g_cnt[b], 1) == 127);
    __syncthreads();

    if (lastflag) {
        const float* pp = g_psum + b * 512;
        sp[tid] = (pp[tid] + pp[tid + 128]) + (pp[tid + 256] + pp[tid + 384]);
        __syncthreads();
        #pragma unroll
        for (int o = 64; o; o >>= 1) {
            if (tid < o) sp[tid] += sp[tid + o];
            __syncthreads();
        }
        const float inv = 1.0f / sp[0];

        float4* ob = (float4*)(out + (b << 11));
        #pragma unroll
        for (int i = 0; i < 4; i++) {
            float4 v = ob[tid + 128 * i];
            v.x *= inv; v.y *= inv; v.z *= inv; v.w *= inv;
            ob[tid + 128 * i] = v;
        }

        // re-zero this batch's g_qcls slice for the next replay
        ((float4*)(g_qcls + b * CC))[tid]       = make_float4(0.f, 0.f, 0.f, 0.f);
        ((float4*)(g_qcls + b * CC))[tid + 128] = make_float4(0.f, 0.f, 0.f, 0.f);

        if (tid == 0) g_cnt[b] = 0;
    }
}

// ---------------------------------------------------------------------------
extern "C" void kernel_launch(void* const* d_in, const int* in_sizes, int n_in,
                              void* d_out, int out_size) {
    const float* x = (const float*)d_in[0];
    const float* w = (const float*)d_in[1];
    if (n_in >= 2 && in_sizes[0] == CC * WS && in_sizes[1] == BB * NTOK * CC) {
        x = (const float*)d_in[1];
        w = (const float*)d_in[0];
    }
    float* out = (float*)d_out;

    k_prep<<<256, 256>>>(x, w);

    // PDL launch: k_logits starts while k_prep runs; device-side
    // cudaGridDependencySynchronize() gates the g_v consumption.
    cudaLaunchConfig_t cfg = {};
    cfg.gridDim  = dim3(128, 16);
    cfg.blockDim = dim3(128);
    cfg.stream   = 0;   // legacy default stream (same as <<<>>> above)
    cudaLaunchAttribute attr[1];
    attr[0].id = cudaLaunchAttributeProgrammaticStreamSerialization;
    attr[0].val.programmaticStreamSerializationAllowed = 1;
    cfg.attrs    = attr;
    cfg.numAttrs = 1;
    cudaLaunchKernelEx(&cfg, k_logits, x, out);
}

// round 17
// speedup vs baseline: 1.0194x; 1.0194x over previous
#include <cuda_runtime.h>
#include <cstdint>

#define BB 16
#define NTOK 2049
#define NK 2048
#define CC 1024
#define WS 3072

__device__ float g_qcls[BB * CC];      // zero-init; atomic accum; re-zeroed by k_logits epilogue
__device__ float g_v[BB * CC];
__device__ float g_psum[BB * 512];     // exp partials: [b][bx*4+warp]
__device__ unsigned g_barP = 0;        // k_prep barrier counter (monotonic, replay-safe)
__device__ int g_cnt[BB] = {0};        // per-batch completion counters (self-reset)

// ---------------------------------------------------------------------------
// helpers
// ---------------------------------------------------------------------------
__device__ __forceinline__ void cpa16(unsigned int smem_addr, const void* gptr) {
    asm volatile("cp.async.cg.shared.global [%0], [%1], 16;"
                 :: "r"(smem_addr), "l"(gptr));
}
#define CPA_COMMIT()  asm volatile("cp.async.commit_group;")
#define CPA_WAIT(N)   asm volatile("cp.async.wait_group %0;" :: "n"(N))

// Grid barrier via monotonic counter (all 256 blocks of k_prep are resident).
__device__ __forceinline__ void gridbar(unsigned* ctr, unsigned G) {
    __syncthreads();
    __threadfence();
    if (threadIdx.x == 0) {
        const unsigned my = atomicAdd(ctr, 1u) + 1u;
        const unsigned tgt = ((my - 1u) / G + 1u) * G;
        while (atomicAdd(ctr, 0u) < tgt) __nanosleep(64);
    }
    __syncthreads();
    __threadfence();
}

// ---------------------------------------------------------------------------
// k_prep: fused q_cls + v. grid 256, 256 thr.
// Fires the PDL trigger FIRST so k_logits can launch and start its
// cp.async x prologue while this kernel computes.
// ---------------------------------------------------------------------------
__global__ __launch_bounds__(256) void k_prep(const float* __restrict__ x,
                                              const float* __restrict__ w) {
    // Arm PDL: once every block has executed this, the dependent launch may start.
    cudaTriggerProgrammaticLaunchCompletion();

    __shared__ float pool[8704];
    const int t   = threadIdx.x;
    const int bid = blockIdx.x;
    const int wid = t >> 5, lane = t & 31;

    // ---------------- Phase A: q_cls partials ----------------
    {
        float* xs  = pool;                // [b][dd] 16x32
        float* red = pool + 512;          // [dg][b][c] 4x16x128
        const int d0 = (bid >> 3) * 32;
        const int c0 = (bid & 7) * 128;

        if (t < 128) {
            const int b = t >> 3, dd = (t & 7) * 4;
            *(float4*)&xs[b * 32 + dd] =
                *(const float4*)&x[(size_t)b * NTOK * CC + d0 + dd];
        }
        __syncthreads();

        const int dg = wid & 3, bg = wid >> 2;
        const int c = c0 + lane * 4;

        float4 a[8];
        #pragma unroll
        for (int j = 0; j < 8; j++) a[j] = make_float4(0.f, 0.f, 0.f, 0.f);

        const float* xb = &xs[bg * 8 * 32];
        #pragma unroll
        for (int i = 0; i < 8; i++) {
            const int dd = dg * 8 + i;
            const float4 w4 = *(const float4*)&w[(size_t)(d0 + dd) * WS + c];
            #pragma unroll
            for (int j = 0; j < 8; j++) {
                const float xv = xb[j * 32 + dd];
                a[j].x = fmaf(w4.x, xv, a[j].x);
                a[j].y = fmaf(w4.y, xv, a[j].y);
                a[j].z = fmaf(w4.z, xv, a[j].z);
                a[j].w = fmaf(w4.w, xv, a[j].w);
            }
        }
        #pragma unroll
        for (int j = 0; j < 8; j++)
            *(float4*)&red[dg * 2048 + (bg * 8 + j) * 128 + lane * 4] = a[j];
        __syncthreads();

        #pragma unroll
        for (int k = 0; k < 8; k++) {
            const int idx = t + 256 * k;             // b = idx>>7, c = idx&127
            const float s = (red[idx] + red[idx + 2048])
                          + (red[idx + 4096] + red[idx + 6144]);
            atomicAdd(&g_qcls[(idx >> 7) * CC + c0 + (idx & 127)], s);
        }
    }

    gridbar(&g_barP, 256);

    // ---------------- Phase B: v ----------------
    {
        float* qs = pool;                 // 8 batches x 1024 = 32KB
        const int bg = bid & 1;
        const int d  = (bid >> 1) * 8 + wid;

        #pragma unroll
        for (int i = 0; i < 8; i++)
            ((float4*)qs)[t + 256 * i] =
                ((const float4*)(g_qcls + bg * 8 * CC))[t + 256 * i];
        __syncthreads();

        const float* wr = w + (size_t)d * WS + CC;
        float acc[8];
        #pragma unroll
        for (int b = 0; b < 8; b++) acc[b] = 0.f;

        #pragma unroll
        for (int i = 0; i < 8; i++) {
            const int cc = i * 128 + lane * 4;
            const float4 w4 = *(const float4*)&wr[cc];
            #pragma unroll
            for (int b = 0; b < 8; b++) {
                const float4 q4 = *(const float4*)&qs[b * CC + cc];
                acc[b] = fmaf(w4.x, q4.x, acc[b]);
                acc[b] = fmaf(w4.y, q4.y, acc[b]);
                acc[b] = fmaf(w4.z, q4.z, acc[b]);
                acc[b] = fmaf(w4.w, q4.w, acc[b]);
            }
        }
        #pragma unroll
        for (int b = 0; b < 8; b++) {
            float a = acc[b];
            #pragma unroll
            for (int o = 16; o; o >>= 1) a += __shfl_xor_sync(0xffffffffu, a, o);
            if (lane == 0) g_v[(bg * 8 + b) * CC + d] = a;
        }
    }
}

// ---------------------------------------------------------------------------
// k_logits (dominant, HBM-bound): grid (128,16), 128 thr, block-wide
// 2-stage cp.async ring, 16 rows/block. PDL: launches under k_prep, issues
// x prologue immediately, then cudaGridDependencySynchronize() before g_v.
// Epilogue: last-block-per-batch normalize.
// ---------------------------------------------------------------------------
__global__ __launch_bounds__(128) void k_logits(const float* __restrict__ x,
                                                float* __restrict__ out) {
    __shared__ float tiles[2 * 4096];
    __shared__ float vsm[CC];
    __shared__ float sp[128];
    __shared__ int lastflag;
    const int b    = blockIdx.y;
    const int bx   = blockIdx.x;
    const int tid  = threadIdx.x;
    const int warp = tid >> 5;
    const int lane = tid & 31;

    const float* xbase = x + ((size_t)b * NTOK + bx * 16 + 1) * CC;
    const unsigned int sb = (unsigned int)__cvta_generic_to_shared(tiles);

    // prologue FIRST — x is launch-stable, overlaps k_prep execution
    #pragma unroll
    for (int k = 0; k < 8; k++)
        cpa16(sb + (k * 512 + tid * 4) * 4, xbase + k * 512 + tid * 4);
    CPA_COMMIT();
    #pragma unroll
    for (int k = 0; k < 8; k++)
        cpa16(sb + (4096 + k * 512 + tid * 4) * 4, xbase + 4096 + k * 512 + tid * 4);
    CPA_COMMIT();

    // HW wait for k_prep completion (deadlock-free, residency-independent)
    cudaGridDependencySynchronize();

    // stage v -> smem -> registers
    #pragma unroll
    for (int i = 0; i < 2; i++)
        ((float4*)vsm)[tid + 128 * i] = ((const float4*)(g_v + b * CC))[tid + 128 * i];
    __syncthreads();
    float4 vr[8];
    #pragma unroll
    for (int i = 0; i < 8; i++) vr[i] = ((const float4*)vsm)[i * 32 + lane];

    float psum = 0.f;

    #pragma unroll
    for (int t = 0; t < 4; t++) {
        if (t == 3) { CPA_WAIT(0); } else { CPA_WAIT(1); }
        __syncthreads();

        const float* buf = tiles + (t & 1) * 4096 + warp * CC;
        float4 a = make_float4(0.f, 0.f, 0.f, 0.f);
        #pragma unroll
        for (int i = 0; i < 8; i++) {
            const float4 xv = ((const float4*)buf)[i * 32 + lane];
            a.x = fmaf(xv.x, vr[i].x, a.x);
            a.y = fmaf(xv.y, vr[i].y, a.y);
            a.z = fmaf(xv.z, vr[i].z, a.z);
            a.w = fmaf(xv.w, vr[i].w, a.w);
        }
        float s = (a.x + a.y) + (a.z + a.w);
        #pragma unroll
        for (int o = 16; o; o >>= 1) s += __shfl_xor_sync(0xffffffffu, s, o);

        if (lane == 0) {
            const float e = __expf(s * 0.03125f);
            out[(b << 11) + bx * 16 + t * 4 + warp] = e;
            psum += e;
        }

        if (t < 2) {
            __syncthreads();
            const int nt = t + 2;
            #pragma unroll
            for (int k = 0; k < 8; k++)
                cpa16(sb + ((nt & 1) * 4096 + k * 512 + tid * 4) * 4,
                      xbase + nt * 4096 + k * 512 + tid * 4);
            CPA_COMMIT();
        }
    }

    if (lane == 0)
        g_psum[b * 512 + bx * 4 + warp] = psum;

    // ---------------- last-block-per-batch normalize ----------------
    __threadfence();
    __syncthreads();
    if (tid == 0)
        lastflag = (atomicAdd(&g_cnt[b], 1) == 127);
    __syncthreads();

    if (lastflag) {
        const float* pp = g_psum + b * 512;
        sp[tid] = (pp[tid] + pp[tid + 128]) + (pp[tid + 256] + pp[tid + 384]);
        __syncthreads();
        #pragma unroll
        for (int o = 64; o; o >>= 1) {
            if (tid < o) sp[tid] += sp[tid + o];
            __syncthreads();
        }
        const float inv = 1.0f / sp[0];

        float4* ob = (float4*)(out + (b << 11));
        #pragma unroll
        for (int i = 0; i < 4; i++) {
            float4 v = ob[tid + 128 * i];
            v.x *= inv; v.y *= inv; v.z *= inv; v.w *= inv;
            ob[tid + 128 * i] = v;
        }

        // re-zero this batch's g_qcls slice for the next replay
        ((float4*)(g_qcls + b * CC))[tid]       = make_float4(0.f, 0.f, 0.f, 0.f);
        ((float4*)(g_qcls + b * CC))[tid + 128] = make_float4(0.f, 0.f, 0.f, 0.f);

        if (tid == 0) g_cnt[b] = 0;
    }
}

// ---------------------------------------------------------------------------
extern "C" void kernel_launch(void* const* d_in, const int* in_sizes, int n_in,
                              void* d_out, int out_size) {
    const float* x = (const float*)d_in[0];
    const float* w = (const float*)d_in[1];
    if (n_in >= 2 && in_sizes[0] == CC * WS && in_sizes[1] == BB * NTOK * CC) {
        x = (const float*)d_in[1];
        w = (const float*)d_in[0];
    }
    float* out = (float*)d_out;

    k_prep<<<256, 256>>>(x, w);

    // PDL launch: k_logits starts while k_prep runs (trigger armed at the
    // top of k_prep); device-side cudaGridDependencySynchronize() gates g_v.
    cudaLaunchConfig_t cfg = {};
    cfg.gridDim  = dim3(128, 16);
    cfg.blockDim = dim3(128);
    cfg.stream   = 0;   // legacy default stream (same as <<<>>> above)
    cudaLaunchAttribute attr[1];
    attr[0].id = cudaLaunchAttributeProgrammaticStreamSerialization;
    attr[0].val.programmaticStreamSerializationAllowed = 1;
    cfg.attrs    = attr;
    cfg.numAttrs = 1;
    cudaLaunchKernelEx(&cfg, k_logits, x, out);
}